// round 15
// baseline (speedup 1.0000x reference)
#include <cuda_runtime.h>
#include <cuda_bf16.h>
#include <mma.h>
#include <math.h>

using namespace nvcuda;

#define T_TOK   8192
#define HIDDEN  5120
#define NHEADS  40
#define NKV     10
#define HD      128
#define QKV_COLS 7680   // (40 + 10 + 10) * 128
#define SEQ     1024

// Scratch (device globals — no cudaMalloc allowed)
__device__ float g_qkv[(size_t)T_TOK * QKV_COLS];   // UNroped; rope applied in attn

// tf32-rounded fp32 operands for the projections
__device__ float g_x32[(size_t)T_TOK * HIDDEN];
__device__ float g_wq32[(size_t)HIDDEN * QKV_COLS];
__device__ float g_wo32[(size_t)NHEADS * HD * HIDDEN];
__device__ float g_o32[(size_t)T_TOK * HIDDEN];     // attention out (tf32-rounded)

// RoPE tables: [pos 0..1023][j 0..63]
__device__ float g_rcos[SEQ * 64];
__device__ float g_rsin[SEQ * 64];

// ---------------------------------------------------------------------------
__device__ __forceinline__ float tf32_rna(float x)
{
    float r;
    asm("cvt.rna.tf32.f32 %0, %1;" : "=f"(r) : "f"(x));
    return r;
}

__global__ __launch_bounds__(256) void rope_table_kernel()
{
    int idx = blockIdx.x * 256 + threadIdx.x;
    if (idx >= SEQ * 64) return;
    int pos = idx >> 6;
    int j = idx & 63;
    float inv_freq = powf(10000.0f, -(float)j / 64.0f);
    float ang = (float)pos * inv_freq;
    g_rcos[idx] = cosf(ang);
    g_rsin[idx] = sinf(ang);
}

// ---------------------------------------------------------------------------
// fp32 -> tf32-rounded fp32 (RNA), vectorized
// ---------------------------------------------------------------------------
__device__ __forceinline__ void round_body(const float* __restrict__ src,
                                           float* __restrict__ dst, long n4)
{
    long i = (long)blockIdx.x * blockDim.x + threadIdx.x;
    if (i >= n4) return;
    float4 a = ((const float4*)src)[i];
    a.x = tf32_rna(a.x); a.y = tf32_rna(a.y);
    a.z = tf32_rna(a.z); a.w = tf32_rna(a.w);
    ((float4*)dst)[i] = a;
}

__global__ __launch_bounds__(256) void round_x(const float* __restrict__ x)
{ round_body(x, g_x32, (long)T_TOK * HIDDEN / 4); }

__global__ __launch_bounds__(256) void round_wqkv(const float* __restrict__ w)
{ round_body(w, g_wq32, (long)HIDDEN * QKV_COLS / 4); }

__global__ __launch_bounds__(256) void round_wo(const float* __restrict__ w)
{ round_body(w, g_wo32, (long)NHEADS * HD * HIDDEN / 4); }

// ---------------------------------------------------------------------------
// cp.async helpers
// ---------------------------------------------------------------------------
__device__ __forceinline__ void cp_async16(void* smem_dst, const void* gsrc)
{
    unsigned d = (unsigned)__cvta_generic_to_shared(smem_dst);
    asm volatile("cp.async.cg.shared.global [%0], [%1], 16;\n" :: "r"(d), "l"(gsrc));
}
__device__ __forceinline__ void cp_commit()
{ asm volatile("cp.async.commit_group;\n"); }
template<int NREM> __device__ __forceinline__ void cp_wait()
{ asm volatile("cp.async.wait_group %0;\n" :: "n"(NREM)); }

// ---------------------------------------------------------------------------
// Single-pass tf32 tensor-core GEMM, 5-stage cp.async pipeline, K-chunk 16.
// C[M,N] = A*B with tf32 inputs (pre-rounded RNA), fp32 accumulate.
// Block 128x128, 256 threads = 8 warps (4x2); warp tile 32x64.
// Wait ladder: allowed pending = min(nchunks-1-ks, GSTAGES-2).
// smem: A[5][128][24] f32 + B[5][16][136] f32 = 104,960 B -> 2 CTAs/SM.
// ---------------------------------------------------------------------------
#define GSTAGES 5
#define GEMM_SMEM ((GSTAGES*128*24 + GSTAGES*16*136) * 4)

__device__ __forceinline__ void gemm_tf32_body(
    const float* __restrict__ A, const float* __restrict__ B,
    float* __restrict__ C, int M, int N, int K)
{
    extern __shared__ __align__(16) char smraw[];
    float* sAb = (float*)smraw;                    // [s][128][24]
    float* sBb = sAb + GSTAGES * 128 * 24;         // [s][16][136]

    const int tid = threadIdx.x;
    const int wid = tid >> 5;
    const int warp_m = wid & 3;
    const int warp_n = wid >> 2;
    const int bm = blockIdx.y * 128;
    const int bn = blockIdx.x * 128;

    // Loaders: A 128 rows x 16 f32 = 8 KB -> 2x16B per thread;
    //          B 16 rows x 128 f32 = 8 KB -> 2x16B per thread.
    const int arow = tid >> 1;
    const int akseg = (tid & 1) * 8;          // floats
    const int brow = tid >> 4;
    const int bcseg = (tid & 15) * 8;         // floats

    const float* ag = A + (size_t)(bm + arow) * K + akseg;
    const float* bg = B + (size_t)brow * N + bn + bcseg;

    #define SA(s, row) (sAb + ((s) * 128 + (row)) * 24)
    #define SB(s, row) (sBb + ((s) * 16 + (row)) * 136)

    auto issue = [&](int s, int k0) {
        cp_async16(SA(s, arow) + akseg,     ag + k0);
        cp_async16(SA(s, arow) + akseg + 4, ag + k0 + 4);
        cp_async16(SB(s, brow) + bcseg,     bg + (size_t)k0 * N);
        cp_async16(SB(s, brow) + bcseg + 4, bg + (size_t)k0 * N + 4);
        cp_commit();
    };

    wmma::fragment<wmma::accumulator, 16, 16, 8, float> c[2][4];
#pragma unroll
    for (int mt = 0; mt < 2; mt++)
#pragma unroll
        for (int nt = 0; nt < 4; nt++) wmma::fill_fragment(c[mt][nt], 0.0f);

    const int nchunks = K / 16;
#pragma unroll
    for (int p = 0; p < GSTAGES - 1; p++) issue(p, p * 16);

    for (int ks = 0; ks < nchunks; ks++) {
        const int rem = nchunks - 1 - ks;
        if      (rem >= 3) cp_wait<3>();
        else if (rem == 2) cp_wait<2>();
        else if (rem == 1) cp_wait<1>();
        else               cp_wait<0>();
        __syncthreads();
        const int s = ks % GSTAGES;

#pragma unroll
        for (int kk = 0; kk < 2; kk++) {      // two k8 steps per 16-chunk
            wmma::fragment<wmma::matrix_a, 16, 16, 8, wmma::precision::tf32, wmma::row_major> fa[2];
            wmma::fragment<wmma::matrix_b, 16, 16, 8, wmma::precision::tf32, wmma::row_major> fb[4];
#pragma unroll
            for (int mt = 0; mt < 2; mt++)
                wmma::load_matrix_sync(fa[mt], SA(s, warp_m * 32 + mt * 16) + kk * 8, 24);
#pragma unroll
            for (int nt = 0; nt < 4; nt++)
                wmma::load_matrix_sync(fb[nt], SB(s, kk * 8) + warp_n * 64 + nt * 16, 136);
#pragma unroll
            for (int mt = 0; mt < 2; mt++)
#pragma unroll
                for (int nt = 0; nt < 4; nt++)
                    wmma::mma_sync(c[mt][nt], fa[mt], fb[nt], c[mt][nt]);
        }

        const int kn = ks + GSTAGES - 1;
        if (kn < nchunks) issue(kn % GSTAGES, kn * 16);
    }

#pragma unroll
    for (int mt = 0; mt < 2; mt++)
#pragma unroll
        for (int nt = 0; nt < 4; nt++) {
            float* cp = C + (size_t)(bm + warp_m * 32 + mt * 16) * N
                          + bn + warp_n * 64 + nt * 16;
            wmma::store_matrix_sync(cp, c[mt][nt], N, wmma::mem_row_major);
        }
    #undef SA
    #undef SB
}

__global__ __launch_bounds__(256) void qkv_gemm_kernel()
{ gemm_tf32_body(g_x32, g_wq32, g_qkv, T_TOK, QKV_COLS, HIDDEN); }

__global__ __launch_bounds__(256) void out_gemm_kernel(float* __restrict__ out)
{ gemm_tf32_body(g_o32, g_wo32, out, T_TOK, HIDDEN, HIDDEN); }

// ---------------------------------------------------------------------------
// wmma flash attention (R10 structure): BQ=128, BK=64, 512 threads, bf16x3.
// Epilogue writes tf32-rounded fp32 to g_o32 for the O projection.
// ---------------------------------------------------------------------------
#define ATTN_SMEM (2*128*136*2 + 2*64*136*2 + 128*72*4 + 128*132*4 + 2*128*4)

__global__ __launch_bounds__(512) void attn_wmma(const int* __restrict__ positions)
{
    extern __shared__ char smraw[];
    __nv_bfloat16* sQh  = (__nv_bfloat16*)smraw;            // 128 x 136
    __nv_bfloat16* sQl  = sQh + 128 * 136;
    __nv_bfloat16* sKVh = sQl + 128 * 136;                  // 64 x 136 (K, then V)
    __nv_bfloat16* sKVl = sKVh + 64 * 136;
    float*         sS   = (float*)(sKVl + 64 * 136);        // 128 x 72 fp32
    __nv_bfloat16* sPh  = (__nv_bfloat16*)sS;               // aliases S
    __nv_bfloat16* sPl  = sPh + 128 * 72;
    float*         sO   = (float*)((char*)sS + 128 * 72 * 4);
    float*         sM   = sO + 128 * 132;
    float*         sL   = sM + 128;

    const int qtile = blockIdx.x;
    const int h     = blockIdx.y;
    const int b     = blockIdx.z;
    const int kvh   = h >> 2;
    const int tid   = threadIdx.x;
    const int wid   = tid >> 5;
    const int warp_m = wid >> 1;
    const int warp_n = wid & 1;

    const float* base = g_qkv + (size_t)b * SEQ * QKV_COLS;
    const int qcol = h * HD;
    const int kcol = (NHEADS + kvh) * HD;
    const int vcol = (NHEADS + NKV + kvh) * HD;
    const float scale = 0.08838834764831845f;

    for (int l = tid; l < 128 * 64; l += 512) {
        int r = l >> 6, j = l & 63;
        int grow = qtile * 128 + r;
        int pos = positions[b * SEQ + grow];
        float cs = g_rcos[pos * 64 + j];
        float sn = g_rsin[pos * 64 + j];
        const float* qr = base + (size_t)grow * QKV_COLS + qcol;
        float x1 = qr[j], x2 = qr[j + 64];
        float y1 = x1 * cs - x2 * sn;
        float y2 = x2 * cs + x1 * sn;
        __nv_bfloat16 h1 = __float2bfloat16(y1);
        __nv_bfloat16 h2 = __float2bfloat16(y2);
        sQh[r * 136 + j]      = h1;
        sQh[r * 136 + j + 64] = h2;
        sQl[r * 136 + j]      = __float2bfloat16(y1 - __bfloat162float(h1));
        sQl[r * 136 + j + 64] = __float2bfloat16(y2 - __bfloat162float(h2));
    }
    for (int l = tid; l < 128 * 132; l += 512) sO[l] = 0.f;
    if (tid < 128) { sM[tid] = -1e30f; sL[tid] = 0.f; }
    __syncthreads();

    const int ktmax = 2 * qtile + 1;
    for (int kt = 0; kt <= ktmax; kt++) {
        for (int l = tid; l < 64 * 64; l += 512) {
            int r = l >> 6, j = l & 63;
            int grow = kt * 64 + r;
            int pos = positions[b * SEQ + grow];
            float cs = g_rcos[pos * 64 + j];
            float sn = g_rsin[pos * 64 + j];
            const float* kr = base + (size_t)grow * QKV_COLS + kcol;
            float x1 = kr[j], x2 = kr[j + 64];
            float y1 = x1 * cs - x2 * sn;
            float y2 = x2 * cs + x1 * sn;
            __nv_bfloat16 h1 = __float2bfloat16(y1);
            __nv_bfloat16 h2 = __float2bfloat16(y2);
            sKVh[r * 136 + j]      = h1;
            sKVh[r * 136 + j + 64] = h2;
            sKVl[r * 136 + j]      = __float2bfloat16(y1 - __bfloat162float(h1));
            sKVl[r * 136 + j + 64] = __float2bfloat16(y2 - __bfloat162float(h2));
        }
        __syncthreads();

        {
            wmma::fragment<wmma::accumulator, 16, 16, 16, float> sacc[2];
#pragma unroll
            for (int st = 0; st < 2; st++) wmma::fill_fragment(sacc[st], 0.0f);
#pragma unroll
            for (int kk = 0; kk < 8; kk++) {
                wmma::fragment<wmma::matrix_a, 16, 16, 16, __nv_bfloat16, wmma::row_major> ah, al;
                wmma::load_matrix_sync(ah, &sQh[(warp_m * 16) * 136 + kk * 16], 136);
                wmma::load_matrix_sync(al, &sQl[(warp_m * 16) * 136 + kk * 16], 136);
#pragma unroll
                for (int st = 0; st < 2; st++) {
                    int n0 = warp_n * 32 + st * 16;
                    wmma::fragment<wmma::matrix_b, 16, 16, 16, __nv_bfloat16, wmma::col_major> bh, bl;
                    wmma::load_matrix_sync(bh, &sKVh[n0 * 136 + kk * 16], 136);
                    wmma::load_matrix_sync(bl, &sKVl[n0 * 136 + kk * 16], 136);
                    wmma::mma_sync(sacc[st], ah, bh, sacc[st]);
                    wmma::mma_sync(sacc[st], ah, bl, sacc[st]);
                    wmma::mma_sync(sacc[st], al, bh, sacc[st]);
                }
            }
#pragma unroll
            for (int st = 0; st < 2; st++)
                wmma::store_matrix_sync(&sS[(warp_m * 16) * 72 + warp_n * 32 + st * 16],
                                        sacc[st], 72, wmma::mem_row_major);
        }
        __syncthreads();

        const int r   = tid >> 2;
        const int sub = tid & 3;
        float evals[16], m_new, factor, lsum;
        {
            for (int l = tid; l < 64 * 64; l += 512) {
                int rr = l >> 6, j = l & 63;
                const float* vr = base + (size_t)(kt * 64 + rr) * QKV_COLS + vcol;
                float v1 = vr[j], v2 = vr[j + 64];
                __nv_bfloat16 vh1 = __float2bfloat16(v1);
                __nv_bfloat16 vh2 = __float2bfloat16(v2);
                sKVh[rr * 136 + j]      = vh1;
                sKVh[rr * 136 + j + 64] = vh2;
                sKVl[rr * 136 + j]      = __float2bfloat16(v1 - __bfloat162float(vh1));
                sKVl[rr * 136 + j + 64] = __float2bfloat16(v2 - __bfloat162float(vh2));
            }

            int grow = qtile * 128 + r;
            float mx = -1e30f;
            float vals[16];
#pragma unroll
            for (int i = 0; i < 16; i++) {
                int j = sub * 16 + i;
                float v = sS[r * 72 + j] * scale;
                if (kt * 64 + j > grow) v = -1e30f;
                vals[i] = v;
                mx = fmaxf(mx, v);
            }
            mx = fmaxf(mx, __shfl_xor_sync(0xffffffffu, mx, 1));
            mx = fmaxf(mx, __shfl_xor_sync(0xffffffffu, mx, 2));
            float m_old = sM[r];
            m_new = fmaxf(m_old, mx);
            factor = __expf(m_old - m_new);
            lsum = 0.f;
#pragma unroll
            for (int i = 0; i < 16; i++) {
                float e = __expf(vals[i] - m_new);
                evals[i] = e;
                lsum += e;
            }
            lsum += __shfl_xor_sync(0xffffffffu, lsum, 1);
            lsum += __shfl_xor_sync(0xffffffffu, lsum, 2);
        }
        __syncthreads();

        {
#pragma unroll
            for (int i = 0; i < 16; i++) {
                float e = evals[i];
                __nv_bfloat16 ph = __float2bfloat16(e);
                sPh[r * 72 + sub * 16 + i] = ph;
                sPl[r * 72 + sub * 16 + i] = __float2bfloat16(e - __bfloat162float(ph));
            }
            if (sub == 0) { sM[r] = m_new; sL[r] = sL[r] * factor + lsum; }
#pragma unroll
            for (int i = 0; i < 32; i++) sO[r * 132 + sub + 4 * i] *= factor;
        }
        __syncthreads();

        {
            wmma::fragment<wmma::matrix_a, 16, 16, 16, __nv_bfloat16, wmma::row_major> pa_h[4], pa_l[4];
#pragma unroll
            for (int kk = 0; kk < 4; kk++) {
                wmma::load_matrix_sync(pa_h[kk], &sPh[(warp_m * 16) * 72 + kk * 16], 72);
                wmma::load_matrix_sync(pa_l[kk], &sPl[(warp_m * 16) * 72 + kk * 16], 72);
            }
#pragma unroll
            for (int nt = 0; nt < 4; nt++) {
                int c0 = warp_n * 64 + nt * 16;
                wmma::fragment<wmma::accumulator, 16, 16, 16, float> oacc;
                wmma::load_matrix_sync(oacc, &sO[(warp_m * 16) * 132 + c0], 132, wmma::mem_row_major);
#pragma unroll
                for (int kk = 0; kk < 4; kk++) {
                    wmma::fragment<wmma::matrix_b, 16, 16, 16, __nv_bfloat16, wmma::row_major> vbh, vbl;
                    wmma::load_matrix_sync(vbh, &sKVh[(kk * 16) * 136 + c0], 136);
                    wmma::load_matrix_sync(vbl, &sKVl[(kk * 16) * 136 + c0], 136);
                    wmma::mma_sync(oacc, pa_h[kk], vbh, oacc);
                    wmma::mma_sync(oacc, pa_h[kk], vbl, oacc);
                    wmma::mma_sync(oacc, pa_l[kk], vbh, oacc);
                }
                wmma::store_matrix_sync(&sO[(warp_m * 16) * 132 + c0], oacc, 132, wmma::mem_row_major);
            }
        }
        __syncthreads();
    }

    // epilogue: normalize + tf32-round + write fp32 to g_o32
    {
        int r = tid >> 2, sub = tid & 3;
        float invl = 1.f / sL[r];
        int grow = qtile * 128 + r;
        float* op = g_o32 + (size_t)(b * SEQ + grow) * HIDDEN + h * HD;
#pragma unroll
        for (int i = 0; i < 8; i++) {
            int c = sub * 32 + i * 4;
            float4 v = *(float4*)&sO[r * 132 + c];
            v.x = tf32_rna(v.x * invl);
            v.y = tf32_rna(v.y * invl);
            v.z = tf32_rna(v.z * invl);
            v.w = tf32_rna(v.w * invl);
            *(float4*)&op[c] = v;
        }
    }
}

// ---------------------------------------------------------------------------
extern "C" void kernel_launch(void* const* d_in, const int* in_sizes, int n_in,
                              void* d_out, int out_size)
{
    const float* x         = nullptr;
    const float* w_qkv     = nullptr;
    const float* w_o       = nullptr;
    const int*   positions = nullptr;

    for (int i = 0; i < n_in; i++) {
        switch (in_sizes[i]) {
            case 41943040: x         = (const float*)d_in[i]; break;
            case 39321600: w_qkv     = (const float*)d_in[i]; break;
            case 26214400: w_o       = (const float*)d_in[i]; break;
            case 8192:     positions = (const int*)  d_in[i]; break;
            default: break;
        }
    }
    float* out = (float*)d_out;

    // 0. rope tables + tf32 rounding of projection operands
    rope_table_kernel<<<SEQ * 64 / 256, 256>>>();
    round_x   <<<(int)((long)T_TOK * HIDDEN / 4 / 256), 256>>>(x);
    round_wqkv<<<(int)((long)HIDDEN * QKV_COLS / 4 / 256), 256>>>(w_qkv);
    round_wo  <<<(int)((long)NHEADS * HD * HIDDEN / 4 / 256), 256>>>(w_o);

    // 1. QKV projection (single-pass tf32 tensor cores) -> g_qkv
    cudaFuncSetAttribute(qkv_gemm_kernel, cudaFuncAttributeMaxDynamicSharedMemorySize, GEMM_SMEM);
    qkv_gemm_kernel<<<dim3(QKV_COLS / 128, T_TOK / 128), 256, GEMM_SMEM>>>();

    // 2. Flash attention (wmma bf16x3, BQ=128, fused rope) -> g_o32 (tf32-rounded)
    cudaFuncSetAttribute(attn_wmma, cudaFuncAttributeMaxDynamicSharedMemorySize, ATTN_SMEM);
    attn_wmma<<<dim3(8, NHEADS, 8), 512, ATTN_SMEM>>>(positions);

    // 3. O projection (single-pass tf32 tensor cores) -> d_out
    cudaFuncSetAttribute(out_gemm_kernel, cudaFuncAttributeMaxDynamicSharedMemorySize, GEMM_SMEM);
    out_gemm_kernel<<<dim3(HIDDEN / 128, T_TOK / 128), 256, GEMM_SMEM>>>(out);
}

// round 16
// speedup vs baseline: 1.4185x; 1.4185x over previous
#include <cuda_runtime.h>
#include <cuda_bf16.h>
#include <mma.h>
#include <math.h>

using namespace nvcuda;

#define T_TOK   8192
#define HIDDEN  5120
#define NHEADS  40
#define NKV     10
#define HD      128
#define QKV_COLS 7680   // (40 + 10 + 10) * 128
#define SEQ     1024

// Scratch (device globals — no cudaMalloc allowed)
__device__ float g_qkv[(size_t)T_TOK * QKV_COLS];   // UNroped; rope applied in attn

// bf16 hi/lo split operands for the projections
__device__ __nv_bfloat16 g_xh[(size_t)T_TOK * HIDDEN];
__device__ __nv_bfloat16 g_xl[(size_t)T_TOK * HIDDEN];
__device__ __nv_bfloat16 g_wqh[(size_t)HIDDEN * QKV_COLS];
__device__ __nv_bfloat16 g_wql[(size_t)HIDDEN * QKV_COLS];
__device__ __nv_bfloat16 g_woh[(size_t)NHEADS * HD * HIDDEN];
__device__ __nv_bfloat16 g_wol[(size_t)NHEADS * HD * HIDDEN];
__device__ __nv_bfloat16 g_oh[(size_t)T_TOK * HIDDEN];   // attention out hi/lo
__device__ __nv_bfloat16 g_ol[(size_t)T_TOK * HIDDEN];

// RoPE tables: [pos 0..1023][j 0..63]
__device__ float g_rcos[SEQ * 64];
__device__ float g_rsin[SEQ * 64];

// ---------------------------------------------------------------------------
__global__ __launch_bounds__(256) void rope_table_kernel()
{
    int idx = blockIdx.x * 256 + threadIdx.x;
    if (idx >= SEQ * 64) return;
    int pos = idx >> 6;
    int j = idx & 63;
    float inv_freq = powf(10000.0f, -(float)j / 64.0f);
    float ang = (float)pos * inv_freq;
    g_rcos[idx] = cosf(ang);
    g_rsin[idx] = sinf(ang);
}

// ---------------------------------------------------------------------------
// fp32 -> (bf16 hi, bf16 lo) split
// ---------------------------------------------------------------------------
__device__ __forceinline__ void split_body(const float* __restrict__ src,
                                           __nv_bfloat16* __restrict__ hi,
                                           __nv_bfloat16* __restrict__ lo,
                                           long n4)
{
    long i = (long)blockIdx.x * blockDim.x + threadIdx.x;
    if (i >= n4) return;
    float4 a = ((const float4*)src)[i];
    __nv_bfloat16 hx = __float2bfloat16(a.x);
    __nv_bfloat16 hy = __float2bfloat16(a.y);
    __nv_bfloat16 hz = __float2bfloat16(a.z);
    __nv_bfloat16 hw = __float2bfloat16(a.w);
    __nv_bfloat162* hp = (__nv_bfloat162*)hi;
    hp[i * 2 + 0] = __nv_bfloat162(hx, hy);
    hp[i * 2 + 1] = __nv_bfloat162(hz, hw);
    __nv_bfloat16 lx = __float2bfloat16(a.x - __bfloat162float(hx));
    __nv_bfloat16 ly = __float2bfloat16(a.y - __bfloat162float(hy));
    __nv_bfloat16 lz = __float2bfloat16(a.z - __bfloat162float(hz));
    __nv_bfloat16 lw = __float2bfloat16(a.w - __bfloat162float(hw));
    __nv_bfloat162* lp = (__nv_bfloat162*)lo;
    lp[i * 2 + 0] = __nv_bfloat162(lx, ly);
    lp[i * 2 + 1] = __nv_bfloat162(lz, lw);
}

__global__ __launch_bounds__(256) void split_x(const float* __restrict__ x)
{ split_body(x, g_xh, g_xl, (long)T_TOK * HIDDEN / 4); }

__global__ __launch_bounds__(256) void split_wqkv(const float* __restrict__ w)
{ split_body(w, g_wqh, g_wql, (long)HIDDEN * QKV_COLS / 4); }

__global__ __launch_bounds__(256) void split_wo(const float* __restrict__ w)
{ split_body(w, g_woh, g_wol, (long)NHEADS * HD * HIDDEN / 4); }

// ---------------------------------------------------------------------------
// cp.async helpers
// ---------------------------------------------------------------------------
__device__ __forceinline__ void cp_async16(void* smem_dst, const void* gsrc)
{
    unsigned d = (unsigned)__cvta_generic_to_shared(smem_dst);
    asm volatile("cp.async.cg.shared.global [%0], [%1], 16;\n" :: "r"(d), "l"(gsrc));
}
__device__ __forceinline__ void cp_commit()
{ asm volatile("cp.async.commit_group;\n"); }
template<int NREM> __device__ __forceinline__ void cp_wait()
{ asm volatile("cp.async.wait_group %0;\n" :: "n"(NREM)); }

// ---------------------------------------------------------------------------
// bf16x3 tensor-core GEMM, 3-stage cp.async pipeline, K-chunk 16.
// Block tile 128(M) x 256(N); 8 warps in 2x4; warp tile 64x64.
// Per epoch per warp: 16 fragment loads vs 48 HMMA (ratio 3, was 2).
// C = Ah*Bh + Ah*Bl + Al*Bh (fp32 acc).
// smem: sA[3][2][128][24] + sB[3][2][16][264] bf16 = 87,552 B -> 2 CTAs/SM.
// ---------------------------------------------------------------------------
#define GSTAGES 3
#define GEMM_SMEM ((GSTAGES*2*128*24 + GSTAGES*2*16*264) * 2)

__device__ __forceinline__ void gemm3_body(
    const __nv_bfloat16* __restrict__ Ah, const __nv_bfloat16* __restrict__ Al,
    const __nv_bfloat16* __restrict__ Bh, const __nv_bfloat16* __restrict__ Bl,
    float* __restrict__ C, int M, int N, int K)
{
    extern __shared__ __align__(16) char smraw[];
    __nv_bfloat16* sAb = (__nv_bfloat16*)smraw;                  // [s][sel][128][24]
    __nv_bfloat16* sBb = sAb + GSTAGES * 2 * 128 * 24;           // [s][sel][16][264]

    const int tid = threadIdx.x;
    const int wid = tid >> 5;
    const int warp_m = wid & 1;        // 2 slabs of 64 rows
    const int warp_n = wid >> 1;       // 4 slabs of 64 cols
    const int bm = blockIdx.y * 128;
    const int bn = blockIdx.x * 256;

    // Loaders: A 128 rows x 16 k (hi+lo): row = tid>>1, kseg = (tid&1)*8 -> 2 cp
    //          B 16 rows x 256 cols (hi+lo): row = tid>>4, col = (tid&15)*16 -> 4 cp
    const int arow = tid >> 1;
    const int akseg = (tid & 1) * 8;
    const int brow = tid >> 4;
    const int bcseg = (tid & 15) * 16;

    const __nv_bfloat16* agh = Ah + (size_t)(bm + arow) * K + akseg;
    const __nv_bfloat16* agl = Al + (size_t)(bm + arow) * K + akseg;
    const __nv_bfloat16* bgh = Bh + (size_t)brow * N + bn + bcseg;
    const __nv_bfloat16* bgl = Bl + (size_t)brow * N + bn + bcseg;

    #define SA(s, sel, row) (sAb + (((s) * 2 + (sel)) * 128 + (row)) * 24)
    #define SB(s, sel, row) (sBb + (((s) * 2 + (sel)) * 16 + (row)) * 264)

    auto issue = [&](int s, int k0) {
        cp_async16(SA(s, 0, arow) + akseg, agh + k0);
        cp_async16(SA(s, 1, arow) + akseg, agl + k0);
        const __nv_bfloat16* bh = bgh + (size_t)k0 * N;
        const __nv_bfloat16* bl = bgl + (size_t)k0 * N;
        cp_async16(SB(s, 0, brow) + bcseg,     bh);
        cp_async16(SB(s, 0, brow) + bcseg + 8, bh + 8);
        cp_async16(SB(s, 1, brow) + bcseg,     bl);
        cp_async16(SB(s, 1, brow) + bcseg + 8, bl + 8);
        cp_commit();
    };

    wmma::fragment<wmma::accumulator, 16, 16, 16, float> c[4][4];
#pragma unroll
    for (int mt = 0; mt < 4; mt++)
#pragma unroll
        for (int nt = 0; nt < 4; nt++) wmma::fill_fragment(c[mt][nt], 0.0f);

    const int nchunks = K / 16;
    issue(0, 0);
    issue(1, 16);

    for (int ks = 0; ks < nchunks; ks++) {
        const int rem = nchunks - 1 - ks;
        if (rem >= 1) cp_wait<1>(); else cp_wait<0>();
        __syncthreads();
        const int s = ks % GSTAGES;

        // A fragments resident: 4 M-tiles x hi/lo
        wmma::fragment<wmma::matrix_a, 16, 16, 16, __nv_bfloat16, wmma::row_major> fah[4], fal[4];
#pragma unroll
        for (int mt = 0; mt < 4; mt++) {
            wmma::load_matrix_sync(fah[mt], SA(s, 0, warp_m * 64 + mt * 16), 24);
            wmma::load_matrix_sync(fal[mt], SA(s, 1, warp_m * 64 + mt * 16), 24);
        }
        // B fragments transient per nt
#pragma unroll
        for (int nt = 0; nt < 4; nt++) {
            wmma::fragment<wmma::matrix_b, 16, 16, 16, __nv_bfloat16, wmma::row_major> fbh, fbl;
            wmma::load_matrix_sync(fbh, SB(s, 0, 0) + warp_n * 64 + nt * 16, 264);
            wmma::load_matrix_sync(fbl, SB(s, 1, 0) + warp_n * 64 + nt * 16, 264);
#pragma unroll
            for (int mt = 0; mt < 4; mt++) {
                wmma::mma_sync(c[mt][nt], fah[mt], fbh, c[mt][nt]);
                wmma::mma_sync(c[mt][nt], fah[mt], fbl, c[mt][nt]);
                wmma::mma_sync(c[mt][nt], fal[mt], fbh, c[mt][nt]);
            }
        }

        const int kn = ks + GSTAGES - 1;
        if (kn < nchunks) issue(kn % GSTAGES, kn * 16);
    }

#pragma unroll
    for (int mt = 0; mt < 4; mt++)
#pragma unroll
        for (int nt = 0; nt < 4; nt++) {
            float* cp = C + (size_t)(bm + warp_m * 64 + mt * 16) * N
                          + bn + warp_n * 64 + nt * 16;
            wmma::store_matrix_sync(cp, c[mt][nt], N, wmma::mem_row_major);
        }
    #undef SA
    #undef SB
}

__global__ __launch_bounds__(256) void qkv_gemm_kernel()
{ gemm3_body(g_xh, g_xl, g_wqh, g_wql, g_qkv, T_TOK, QKV_COLS, HIDDEN); }

__global__ __launch_bounds__(256) void out_gemm_kernel(float* __restrict__ out)
{ gemm3_body(g_oh, g_ol, g_woh, g_wol, out, T_TOK, HIDDEN, HIDDEN); }

// ---------------------------------------------------------------------------
// wmma flash attention (unchanged from R10): BQ=128, BK=64, 512 threads.
// ---------------------------------------------------------------------------
#define ATTN_SMEM (2*128*136*2 + 2*64*136*2 + 128*72*4 + 128*132*4 + 2*128*4)

__global__ __launch_bounds__(512) void attn_wmma(const int* __restrict__ positions)
{
    extern __shared__ char smraw[];
    __nv_bfloat16* sQh  = (__nv_bfloat16*)smraw;            // 128 x 136
    __nv_bfloat16* sQl  = sQh + 128 * 136;
    __nv_bfloat16* sKVh = sQl + 128 * 136;                  // 64 x 136 (K, then V)
    __nv_bfloat16* sKVl = sKVh + 64 * 136;
    float*         sS   = (float*)(sKVl + 64 * 136);        // 128 x 72 fp32
    __nv_bfloat16* sPh  = (__nv_bfloat16*)sS;               // aliases S
    __nv_bfloat16* sPl  = sPh + 128 * 72;
    float*         sO   = (float*)((char*)sS + 128 * 72 * 4);
    float*         sM   = sO + 128 * 132;
    float*         sL   = sM + 128;

    const int qtile = blockIdx.x;
    const int h     = blockIdx.y;
    const int b     = blockIdx.z;
    const int kvh   = h >> 2;
    const int tid   = threadIdx.x;
    const int wid   = tid >> 5;
    const int warp_m = wid >> 1;
    const int warp_n = wid & 1;

    const float* base = g_qkv + (size_t)b * SEQ * QKV_COLS;
    const int qcol = h * HD;
    const int kcol = (NHEADS + kvh) * HD;
    const int vcol = (NHEADS + NKV + kvh) * HD;
    const float scale = 0.08838834764831845f;

    for (int l = tid; l < 128 * 64; l += 512) {
        int r = l >> 6, j = l & 63;
        int grow = qtile * 128 + r;
        int pos = positions[b * SEQ + grow];
        float cs = g_rcos[pos * 64 + j];
        float sn = g_rsin[pos * 64 + j];
        const float* qr = base + (size_t)grow * QKV_COLS + qcol;
        float x1 = qr[j], x2 = qr[j + 64];
        float y1 = x1 * cs - x2 * sn;
        float y2 = x2 * cs + x1 * sn;
        __nv_bfloat16 h1 = __float2bfloat16(y1);
        __nv_bfloat16 h2 = __float2bfloat16(y2);
        sQh[r * 136 + j]      = h1;
        sQh[r * 136 + j + 64] = h2;
        sQl[r * 136 + j]      = __float2bfloat16(y1 - __bfloat162float(h1));
        sQl[r * 136 + j + 64] = __float2bfloat16(y2 - __bfloat162float(h2));
    }
    for (int l = tid; l < 128 * 132; l += 512) sO[l] = 0.f;
    if (tid < 128) { sM[tid] = -1e30f; sL[tid] = 0.f; }
    __syncthreads();

    const int ktmax = 2 * qtile + 1;
    for (int kt = 0; kt <= ktmax; kt++) {
        for (int l = tid; l < 64 * 64; l += 512) {
            int r = l >> 6, j = l & 63;
            int grow = kt * 64 + r;
            int pos = positions[b * SEQ + grow];
            float cs = g_rcos[pos * 64 + j];
            float sn = g_rsin[pos * 64 + j];
            const float* kr = base + (size_t)grow * QKV_COLS + kcol;
            float x1 = kr[j], x2 = kr[j + 64];
            float y1 = x1 * cs - x2 * sn;
            float y2 = x2 * cs + x1 * sn;
            __nv_bfloat16 h1 = __float2bfloat16(y1);
            __nv_bfloat16 h2 = __float2bfloat16(y2);
            sKVh[r * 136 + j]      = h1;
            sKVh[r * 136 + j + 64] = h2;
            sKVl[r * 136 + j]      = __float2bfloat16(y1 - __bfloat162float(h1));
            sKVl[r * 136 + j + 64] = __float2bfloat16(y2 - __bfloat162float(h2));
        }
        __syncthreads();

        {
            wmma::fragment<wmma::accumulator, 16, 16, 16, float> sacc[2];
#pragma unroll
            for (int st = 0; st < 2; st++) wmma::fill_fragment(sacc[st], 0.0f);
#pragma unroll
            for (int kk = 0; kk < 8; kk++) {
                wmma::fragment<wmma::matrix_a, 16, 16, 16, __nv_bfloat16, wmma::row_major> ah, al;
                wmma::load_matrix_sync(ah, &sQh[(warp_m * 16) * 136 + kk * 16], 136);
                wmma::load_matrix_sync(al, &sQl[(warp_m * 16) * 136 + kk * 16], 136);
#pragma unroll
                for (int st = 0; st < 2; st++) {
                    int n0 = warp_n * 32 + st * 16;
                    wmma::fragment<wmma::matrix_b, 16, 16, 16, __nv_bfloat16, wmma::col_major> bh, bl;
                    wmma::load_matrix_sync(bh, &sKVh[n0 * 136 + kk * 16], 136);
                    wmma::load_matrix_sync(bl, &sKVl[n0 * 136 + kk * 16], 136);
                    wmma::mma_sync(sacc[st], ah, bh, sacc[st]);
                    wmma::mma_sync(sacc[st], ah, bl, sacc[st]);
                    wmma::mma_sync(sacc[st], al, bh, sacc[st]);
                }
            }
#pragma unroll
            for (int st = 0; st < 2; st++)
                wmma::store_matrix_sync(&sS[(warp_m * 16) * 72 + warp_n * 32 + st * 16],
                                        sacc[st], 72, wmma::mem_row_major);
        }
        __syncthreads();

        const int r   = tid >> 2;
        const int sub = tid & 3;
        float evals[16], m_new, factor, lsum;
        {
            for (int l = tid; l < 64 * 64; l += 512) {
                int rr = l >> 6, j = l & 63;
                const float* vr = base + (size_t)(kt * 64 + rr) * QKV_COLS + vcol;
                float v1 = vr[j], v2 = vr[j + 64];
                __nv_bfloat16 vh1 = __float2bfloat16(v1);
                __nv_bfloat16 vh2 = __float2bfloat16(v2);
                sKVh[rr * 136 + j]      = vh1;
                sKVh[rr * 136 + j + 64] = vh2;
                sKVl[rr * 136 + j]      = __float2bfloat16(v1 - __bfloat162float(vh1));
                sKVl[rr * 136 + j + 64] = __float2bfloat16(v2 - __bfloat162float(vh2));
            }

            int grow = qtile * 128 + r;
            float mx = -1e30f;
            float vals[16];
#pragma unroll
            for (int i = 0; i < 16; i++) {
                int j = sub * 16 + i;
                float v = sS[r * 72 + j] * scale;
                if (kt * 64 + j > grow) v = -1e30f;
                vals[i] = v;
                mx = fmaxf(mx, v);
            }
            mx = fmaxf(mx, __shfl_xor_sync(0xffffffffu, mx, 1));
            mx = fmaxf(mx, __shfl_xor_sync(0xffffffffu, mx, 2));
            float m_old = sM[r];
            m_new = fmaxf(m_old, mx);
            factor = __expf(m_old - m_new);
            lsum = 0.f;
#pragma unroll
            for (int i = 0; i < 16; i++) {
                float e = __expf(vals[i] - m_new);
                evals[i] = e;
                lsum += e;
            }
            lsum += __shfl_xor_sync(0xffffffffu, lsum, 1);
            lsum += __shfl_xor_sync(0xffffffffu, lsum, 2);
        }
        __syncthreads();

        {
#pragma unroll
            for (int i = 0; i < 16; i++) {
                float e = evals[i];
                __nv_bfloat16 ph = __float2bfloat16(e);
                sPh[r * 72 + sub * 16 + i] = ph;
                sPl[r * 72 + sub * 16 + i] = __float2bfloat16(e - __bfloat162float(ph));
            }
            if (sub == 0) { sM[r] = m_new; sL[r] = sL[r] * factor + lsum; }
#pragma unroll
            for (int i = 0; i < 32; i++) sO[r * 132 + sub + 4 * i] *= factor;
        }
        __syncthreads();

        {
            wmma::fragment<wmma::matrix_a, 16, 16, 16, __nv_bfloat16, wmma::row_major> pa_h[4], pa_l[4];
#pragma unroll
            for (int kk = 0; kk < 4; kk++) {
                wmma::load_matrix_sync(pa_h[kk], &sPh[(warp_m * 16) * 72 + kk * 16], 72);
                wmma::load_matrix_sync(pa_l[kk], &sPl[(warp_m * 16) * 72 + kk * 16], 72);
            }
#pragma unroll
            for (int nt = 0; nt < 4; nt++) {
                int c0 = warp_n * 64 + nt * 16;
                wmma::fragment<wmma::accumulator, 16, 16, 16, float> oacc;
                wmma::load_matrix_sync(oacc, &sO[(warp_m * 16) * 132 + c0], 132, wmma::mem_row_major);
#pragma unroll
                for (int kk = 0; kk < 4; kk++) {
                    wmma::fragment<wmma::matrix_b, 16, 16, 16, __nv_bfloat16, wmma::row_major> vbh, vbl;
                    wmma::load_matrix_sync(vbh, &sKVh[(kk * 16) * 136 + c0], 136);
                    wmma::load_matrix_sync(vbl, &sKVl[(kk * 16) * 136 + c0], 136);
                    wmma::mma_sync(oacc, pa_h[kk], vbh, oacc);
                    wmma::mma_sync(oacc, pa_h[kk], vbl, oacc);
                    wmma::mma_sync(oacc, pa_l[kk], vbh, oacc);
                }
                wmma::store_matrix_sync(&sO[(warp_m * 16) * 132 + c0], oacc, 132, wmma::mem_row_major);
            }
        }
        __syncthreads();
    }

    {
        int r = tid >> 2, sub = tid & 3;
        float invl = 1.f / sL[r];
        int grow = qtile * 128 + r;
        size_t rowoff = (size_t)(b * SEQ + grow) * HIDDEN + h * HD;
#pragma unroll
        for (int i = 0; i < 8; i++) {
            int c = sub * 32 + i * 4;
            float4 v = *(float4*)&sO[r * 132 + c];
            v.x *= invl; v.y *= invl; v.z *= invl; v.w *= invl;
            __nv_bfloat16 hx = __float2bfloat16(v.x);
            __nv_bfloat16 hy = __float2bfloat16(v.y);
            __nv_bfloat16 hz = __float2bfloat16(v.z);
            __nv_bfloat16 hw = __float2bfloat16(v.w);
            *(__nv_bfloat162*)&g_oh[rowoff + c]     = __nv_bfloat162(hx, hy);
            *(__nv_bfloat162*)&g_oh[rowoff + c + 2] = __nv_bfloat162(hz, hw);
            *(__nv_bfloat162*)&g_ol[rowoff + c]     =
                __nv_bfloat162(__float2bfloat16(v.x - __bfloat162float(hx)),
                               __float2bfloat16(v.y - __bfloat162float(hy)));
            *(__nv_bfloat162*)&g_ol[rowoff + c + 2] =
                __nv_bfloat162(__float2bfloat16(v.z - __bfloat162float(hz)),
                               __float2bfloat16(v.w - __bfloat162float(hw)));
        }
    }
}

// ---------------------------------------------------------------------------
extern "C" void kernel_launch(void* const* d_in, const int* in_sizes, int n_in,
                              void* d_out, int out_size)
{
    const float* x         = nullptr;
    const float* w_qkv     = nullptr;
    const float* w_o       = nullptr;
    const int*   positions = nullptr;

    for (int i = 0; i < n_in; i++) {
        switch (in_sizes[i]) {
            case 41943040: x         = (const float*)d_in[i]; break;
            case 39321600: w_qkv     = (const float*)d_in[i]; break;
            case 26214400: w_o       = (const float*)d_in[i]; break;
            case 8192:     positions = (const int*)  d_in[i]; break;
            default: break;
        }
    }
    float* out = (float*)d_out;

    // 0. rope tables + projection operand splits
    rope_table_kernel<<<SEQ * 64 / 256, 256>>>();
    split_x   <<<(int)((long)T_TOK * HIDDEN / 4 / 256), 256>>>(x);
    split_wqkv<<<(int)((long)HIDDEN * QKV_COLS / 4 / 256), 256>>>(w_qkv);
    split_wo  <<<(int)((long)NHEADS * HD * HIDDEN / 4 / 256), 256>>>(w_o);

    // 1. QKV projection (bf16x3, block 128x256, warp 64x64) -> g_qkv
    cudaFuncSetAttribute(qkv_gemm_kernel, cudaFuncAttributeMaxDynamicSharedMemorySize, GEMM_SMEM);
    qkv_gemm_kernel<<<dim3(QKV_COLS / 256, T_TOK / 128), 256, GEMM_SMEM>>>();

    // 2. Flash attention (wmma, BQ=128, fused rope + output split) -> g_oh/g_ol
    cudaFuncSetAttribute(attn_wmma, cudaFuncAttributeMaxDynamicSharedMemorySize, ATTN_SMEM);
    attn_wmma<<<dim3(8, NHEADS, 8), 512, ATTN_SMEM>>>(positions);

    // 3. O projection (bf16x3, block 128x256, warp 64x64) -> d_out
    cudaFuncSetAttribute(out_gemm_kernel, cudaFuncAttributeMaxDynamicSharedMemorySize, GEMM_SMEM);
    out_gemm_kernel<<<dim3(HIDDEN / 256, T_TOK / 128), 256, GEMM_SMEM>>>(out);
}